// round 2
// baseline (speedup 1.0000x reference)
#include <cuda_runtime.h>
#include <cuda_bf16.h>
#include <math.h>
#include <stdint.h>

// Problem constants
#define Bn  32
#define Cc  80
#define TXn 512
#define TYn 2048
#define K2  160          // stacked K: [scale(80); mean*scale(80)]
#define NEGV (-1e9f)
#define LOG2PI 1.8378770664093453f
#define CHY 512          // y-chunk for gemm/fwd pipelining
#define NCH (TYn/CHY)    // 4

// Output layout (flat f32, reference return order)
#define Z_OFF        0
#define YMEAN_OFF    (Bn*Cc*TYn)
#define YLOG_OFF     (2*Bn*Cc*TYn)
#define ATTN_OFF     (3*Bn*Cc*TYn)
#define ODUR_OFF     (ATTN_OFF + Bn*TYn*TXn)
#define OADUR_OFF    (ODUR_OFF + Bn*TXn)

// -------------------- scratch (__device__ globals) --------------------------
__device__ float    g_W[Bn*K2*TXn];              // [b][k][x]
__device__ float    g_Z[Bn*K2*TYn];              // [b][k][y]
__device__ float    g_rowA[Bn*TXn];              // logp1+logp4 per (b,x)
__device__ float    g_logpT[(size_t)Bn*TYn*TXn]; // 134 MB [b][y][x]
__device__ unsigned g_dbits[(size_t)Bn*TYn*32];  // dir bits, 16/lane-word
__device__ float    g_vst[Bn*TXn];               // fwd DP state between chunks
__device__ int      g_xy[Bn*TYn];                // alignment index per (b,y)
__device__ int      g_cnt[Bn*TXn];               // per-x duration counts

// -------------------- K1: per-(b,x) prep -------------------------------------
__global__ void prepx_kernel(const float* __restrict__ om,
                             const float* __restrict__ ols,
                             const float* __restrict__ odur,
                             float* __restrict__ out)
{
    int i = blockIdx.x * blockDim.x + threadIdx.x;
    if (i >= Bn*TXn) return;
    int b = i / TXn, x = i % TXn;
    const float* omb = om  + (size_t)b*Cc*TXn + x;
    const float* olb = ols + (size_t)b*Cc*TXn + x;
    float* wS = g_W + (size_t)b*K2*TXn + x;
    float sa = 0.f;
    #pragma unroll 4
    for (int c = 0; c < Cc; c++) {
        float l  = olb[(size_t)c*TXn];
        float sc = expf(-2.f*l);
        float m  = omb[(size_t)c*TXn];
        wS[(size_t)c*TXn]        = sc;
        wS[(size_t)(Cc+c)*TXn]   = m*sc;
        sa += -0.5f*LOG2PI - l - 0.5f*m*m*sc;
    }
    g_rowA[i] = sa;
    g_cnt[i]  = 0;
    out[ODUR_OFF + i] = odur[i];
}

// -------------------- K2: z masking + Z matrix --------------------------------
__global__ void prepz_kernel(const float* __restrict__ z,
                             const int* __restrict__ yl,
                             float* __restrict__ out)
{
    int i = blockIdx.x * blockDim.x + threadIdx.x;
    if (i >= Bn*Cc*TYn) return;
    int b = i / (Cc*TYn);
    int r = i % (Cc*TYn);
    int c = r / TYn;
    int y = r % TYn;
    float zv = z[i];
    if (y >= yl[b]) zv = 0.f;
    out[Z_OFF + i] = zv;
    size_t zb = (size_t)b*K2*TYn;
    g_Z[zb + (size_t)c*TYn + y]      = -0.5f*zv*zv;
    g_Z[zb + (size_t)(Cc+c)*TYn + y] = zv;
}

// -------------------- K3: logp GEMM (128x128 tile, 256 thr, 8x8/thr) ----------
__global__ void __launch_bounds__(256, 2)
gemm_kernel(const int* __restrict__ xl, const int* __restrict__ yl, int ybase)
{
    int b  = blockIdx.z;
    int x0 = blockIdx.x * 128;
    int y0 = ybase + blockIdx.y * 128;
    int xlen = xl[b], ylen = yl[b];
    if (x0 >= xlen || y0 >= ylen) return;

    __shared__ float zs[16][128];   // k x y
    __shared__ float ws[16][128];   // k x x

    int tid  = threadIdx.x;
    int lrow = tid >> 4;            // 0..15
    int lcol = (tid & 15) << 3;     // 0..120, thread loads 8 floats (2 f4)
    int ty   = tid >> 4;            // 0..15 (y micro 8)
    int tx   = tid & 15;            // 0..15 (x micro 8)

    const float* Zb = g_Z + (size_t)b*K2*TYn;
    const float* Wb = g_W + (size_t)b*K2*TXn;

    float acc[8][8] = {};

    for (int k0 = 0; k0 < K2; k0 += 16) {
        const float* zp = Zb + (size_t)(k0+lrow)*TYn + y0 + lcol;
        const float* wp = Wb + (size_t)(k0+lrow)*TXn + x0 + lcol;
        *(float4*)&zs[lrow][lcol]   = *(const float4*)zp;
        *(float4*)&zs[lrow][lcol+4] = *(const float4*)(zp+4);
        *(float4*)&ws[lrow][lcol]   = *(const float4*)wp;
        *(float4*)&ws[lrow][lcol+4] = *(const float4*)(wp+4);
        __syncthreads();
        #pragma unroll
        for (int k = 0; k < 16; k++) {
            float4 z0 = *(float4*)&zs[k][ty<<3];
            float4 z1 = *(float4*)&zs[k][(ty<<3)+4];
            float4 w0 = *(float4*)&ws[k][tx<<3];
            float4 w1 = *(float4*)&ws[k][(tx<<3)+4];
            float za[8] = {z0.x,z0.y,z0.z,z0.w,z1.x,z1.y,z1.z,z1.w};
            float wa[8] = {w0.x,w0.y,w0.z,w0.w,w1.x,w1.y,w1.z,w1.w};
            #pragma unroll
            for (int i = 0; i < 8; i++)
                #pragma unroll
                for (int j = 0; j < 8; j++)
                    acc[i][j] += za[i]*wa[j];
        }
        __syncthreads();
    }

    float ra[8];
    #pragma unroll
    for (int j = 0; j < 8; j++)
        ra[j] = g_rowA[b*TXn + x0 + (tx<<3) + j];

    #pragma unroll
    for (int i = 0; i < 8; i++) {
        int y = y0 + (ty<<3) + i;
        float* op = g_logpT + ((size_t)b*TYn + y)*TXn + x0 + (tx<<3);
        float4 o0, o1;
        float* p0 = (float*)&o0; float* p1 = (float*)&o1;
        bool yok = (y < ylen);
        #pragma unroll
        for (int j = 0; j < 4; j++) {
            int xa = x0 + (tx<<3) + j;
            int xb = xa + 4;
            p0[j] = (yok && xa < xlen) ? (acc[i][j]   + ra[j])   : 0.f;
            p1[j] = (yok && xb < xlen) ? (acc[i][j+4] + ra[j+4]) : 0.f;
        }
        *(float4*)op       = o0;
        *(float4*)(op + 4) = o1;
    }
}

// -------------------- K4: forward Viterbi chunk (1 warp per batch) ------------
__global__ void __launch_bounds__(32)
fwd_kernel(const int* __restrict__ xl, const int* __restrict__ yl, int j0c)
{
    int b = blockIdx.x, lane = threadIdx.x;
    int xlen = xl[b], ylen = yl[b];
    int jend = min(ylen, j0c + CHY);
    if (j0c >= jend) return;

    int xb = lane * 16;
    bool act = (xb < xlen);
    unsigned fbits;
    if (!act)                 fbits = 0xFFFFu;
    else if (xb + 16 <= xlen) fbits = 0u;
    else                      fbits = (0xFFFFu << (xlen - xb)) & 0xFFFFu;

    float v[16];
    if (j0c == 0) {
        #pragma unroll
        for (int i = 0; i < 16; i++) v[i] = 0.f;
    } else {
        float4* vs = (float4*)&g_vst[b*TXn + xb];
        #pragma unroll
        for (int q = 0; q < 4; q++) ((float4*)v)[q] = vs[q];
    }

    const float4* colbase = (const float4*)(g_logpT + (size_t)b*TYn*TXn + xb);
    const int stride4 = TXn / 4;

    float4 cb[4][4];
    #pragma unroll
    for (int d = 0; d < 4; d++) {
        if (act && j0c + d < jend) {
            const float4* p = colbase + (size_t)(j0c+d) * stride4;
            cb[d][0]=p[0]; cb[d][1]=p[1]; cb[d][2]=p[2]; cb[d][3]=p[3];
        }
    }

    for (int j = j0c; j < jend; j++) {
        int sl = j & 3;
        float c[16];
        ((float4*)c)[0]=cb[sl][0]; ((float4*)c)[1]=cb[sl][1];
        ((float4*)c)[2]=cb[sl][2]; ((float4*)c)[3]=cb[sl][3];

        if (act && j + 4 < jend) {
            const float4* p = colbase + (size_t)(j+4) * stride4;
            cb[sl][0]=p[0]; cb[sl][1]=p[1]; cb[sl][2]=p[2]; cb[sl][3]=p[3];
        }

        float left = __shfl_up_sync(0xFFFFFFFFu, v[15], 1);
        if (lane == 0) left = NEGV;

        unsigned w = 0u;
        if (act) {
            float pv = left;
            if (j < xlen - 1) {           // ramp phase: x>j must be NEG
                #pragma unroll
                for (int i = 0; i < 16; i++) {
                    float old = v[i];
                    bool  di  = old >= pv;
                    float vm  = di ? old : pv;
                    float nv  = vm + c[i];
                    if (xb + i > j) nv = NEGV;
                    w |= di ? (1u << i) : 0u;
                    pv = old;
                    v[i] = nv;
                }
            } else {                      // fast phase: no masking
                #pragma unroll
                for (int i = 0; i < 16; i++) {
                    float old = v[i];
                    bool  di  = old >= pv;
                    float vm  = di ? old : pv;
                    w |= di ? (1u << i) : 0u;
                    pv = old;
                    v[i] = vm + c[i];
                }
            }
        }
        w |= fbits;
        g_dbits[((size_t)b*TYn + j)*32 + lane] = w;
    }

    // persist DP state for next chunk
    float4* vs = (float4*)&g_vst[b*TXn + xb];
    #pragma unroll
    for (int q = 0; q < 4; q++) vs[q] = ((float4*)v)[q];
}

// -------------------- K5: backtrack + duration count (1 warp per batch) -------
__global__ void __launch_bounds__(32)
bwd_kernel(const int* __restrict__ xl, const int* __restrict__ yl)
{
    int b = blockIdx.x, lane = threadIdx.x;
    int xlen = xl[b], ylen = yl[b];

    for (int j = ylen + lane; j < TYn; j += 32) g_xy[b*TYn + j] = 0;

    int idx = xlen - 1;
    for (int jhi = ylen - 1; jhi >= 0; jhi -= 32) {
        int steps = min(32, jhi + 1);
        int j = jhi - lane;
        int w0 = idx >> 4;
        unsigned d0 = 0xFFFFu, d1 = 0xFFFFu, d2 = 0xFFFFu;
        if (lane < steps) {
            const unsigned* p = g_dbits + ((size_t)b*TYn + j)*32;
            d0 = p[w0];
            if (w0 >= 1) d1 = p[w0-1];
            if (w0 >= 2) d2 = p[w0-2];
        }
        int myidx = 0;
        for (int s = 0; s < steps; s++) {
            int wsel = w0 - (idx >> 4);
            unsigned sel  = (wsel == 0) ? d0 : ((wsel == 1) ? d1 : d2);
            unsigned word = __shfl_sync(0xFFFFFFFFu, sel, s);
            if (lane == s) myidx = idx;
            idx += (int)((word >> (idx & 15)) & 1u) - 1;
        }
        if (lane < steps) {
            g_xy[b*TYn + jhi - lane] = myidx;
            atomicAdd(&g_cnt[b*TXn + myidx], 1);
        }
    }
}

// -------------------- K6: y_mean / y_log_scale gathers -------------------------
__global__ void gather_kernel(const float* __restrict__ om,
                              const float* __restrict__ ols,
                              const int* __restrict__ yl,
                              float* __restrict__ out)
{
    int i = blockIdx.x * blockDim.x + threadIdx.x;
    if (i >= Bn*Cc*TYn) return;
    int b = i / (Cc*TYn);
    int r = i % (Cc*TYn);
    int c = r / TYn;
    int y = r % TYn;
    float m = 0.f, s = 0.f;
    if (y < yl[b]) {
        int x = g_xy[b*TYn + y];
        m = om [(size_t)(b*Cc + c)*TXn + x];
        s = ols[(size_t)(b*Cc + c)*TXn + x];
    }
    out[YMEAN_OFF + i] = m;
    out[YLOG_OFF  + i] = s;
}

// -------------------- K7: attn_out (zero + one-hot scatter) --------------------
__global__ void attn_kernel(const int* __restrict__ yl, float* __restrict__ out)
{
    int y = blockIdx.x, b = blockIdx.y, t = threadIdx.x;
    int xi = (y < yl[b]) ? g_xy[b*TYn + y] : -1;
    int x4 = t << 2;
    float4 r = make_float4(0.f, 0.f, 0.f, 0.f);
    if (xi >= x4 && xi < x4 + 4) ((float*)&r)[xi - x4] = 1.0f;
    *(float4*)&out[ATTN_OFF + ((size_t)b*TYn + y)*TXn + x4] = r;
}

// -------------------- K8: o_attn_dur --------------------------------------------
__global__ void dur_kernel(const int* __restrict__ xl, float* __restrict__ out)
{
    int i = blockIdx.x * blockDim.x + threadIdx.x;
    if (i >= Bn*TXn) return;
    int b = i / TXn, x = i % TXn;
    out[OADUR_OFF + i] = (x < xl[b]) ? log1pf((float)g_cnt[i]) : 0.f;
}

// -------------------- launch -----------------------------------------------------
extern "C" void kernel_launch(void* const* d_in, const int* in_sizes, int n_in,
                              void* d_out, int out_size)
{
    const float* om   = (const float*)d_in[0];
    const float* ols  = (const float*)d_in[1];
    const float* odur = (const float*)d_in[2];
    const float* z    = (const float*)d_in[3];
    const int*   xlen = (const int*)  d_in[4];
    const int*   ylen = (const int*)  d_in[5];
    float* out = (float*)d_out;

    // persistent side stream + events (created once, outside capture on the
    // correctness call; identical work every call)
    static cudaStream_t s2;
    static cudaEvent_t evA, evG[NCH], evB, evT;
    static bool init_done = false;
    if (!init_done) {
        cudaStreamCreateWithFlags(&s2, cudaStreamNonBlocking);
        cudaEventCreateWithFlags(&evA, cudaEventDisableTiming);
        for (int k = 0; k < NCH; k++)
            cudaEventCreateWithFlags(&evG[k], cudaEventDisableTiming);
        cudaEventCreateWithFlags(&evB, cudaEventDisableTiming);
        cudaEventCreateWithFlags(&evT, cudaEventDisableTiming);
        init_done = true;
    }

    // prep on main (capture) stream
    prepx_kernel<<<(Bn*TXn + 255)/256, 256>>>(om, ols, odur, out);
    prepz_kernel<<<(Bn*Cc*TYn + 255)/256, 256>>>(z, ylen, out);
    cudaEventRecord(evA, 0);

    // GEMM chunks on forked stream
    cudaStreamWaitEvent(s2, evA, 0);
    for (int k = 0; k < NCH; k++) {
        gemm_kernel<<<dim3(TXn/128, CHY/128, Bn), 256, 0, s2>>>(xlen, ylen, k*CHY);
        cudaEventRecord(evG[k], s2);
    }

    // forward DP chunks on main stream, each gated on its GEMM chunk
    for (int k = 0; k < NCH; k++) {
        cudaStreamWaitEvent(0, evG[k], 0);
        fwd_kernel<<<Bn, 32>>>(xlen, ylen, k*CHY);
    }

    // backtrack (+counts) on main stream
    bwd_kernel<<<Bn, 32>>>(xlen, ylen);
    cudaEventRecord(evB, 0);

    // tail: attn scatter forked to s2, gathers on main
    cudaStreamWaitEvent(s2, evB, 0);
    attn_kernel<<<dim3(TYn, Bn), 128, 0, s2>>>(ylen, out);
    cudaEventRecord(evT, s2);

    gather_kernel<<<(Bn*Cc*TYn + 255)/256, 256>>>(om, ols, ylen, out);
    dur_kernel<<<(Bn*TXn + 255)/256, 256>>>(xlen, out);
    cudaStreamWaitEvent(0, evT, 0);   // join fork before capture ends
}

// round 3
// speedup vs baseline: 2.9238x; 2.9238x over previous
#include <cuda_runtime.h>
#include <cuda_bf16.h>
#include <math.h>
#include <stdint.h>

// Problem constants
#define Bn  32
#define Cc  80
#define TXn 512
#define TYn 2048
#define K2  160          // stacked K: [scale(80); mean*scale(80)]
#define NEGV (-1e9f)
#define LOG2PI 1.8378770664093453f

// Output layout (flat f32, reference return order)
#define Z_OFF        0
#define YMEAN_OFF    (Bn*Cc*TYn)
#define YLOG_OFF     (2*Bn*Cc*TYn)
#define ATTN_OFF     (3*Bn*Cc*TYn)
#define ODUR_OFF     (ATTN_OFF + Bn*TYn*TXn)
#define OADUR_OFF    (ODUR_OFF + Bn*TXn)

// -------------------- scratch (__device__ globals) --------------------------
__device__ float    g_W[Bn*K2*TXn];              // [b][k][x]
__device__ float    g_Z[Bn*K2*TYn];              // [b][k][y]
__device__ float    g_rowA[Bn*TXn];              // logp1+logp4 per (b,x)
__device__ float    g_logpT[(size_t)Bn*TYn*TXn]; // 134 MB [b][y][x]
__device__ unsigned g_dbits[(size_t)Bn*TYn*16];  // dir bits, 32/warp-word
__device__ int      g_xy[Bn*TYn];                // alignment index per (b,y)
__device__ int      g_cnt[Bn*TXn];               // per-x duration counts

// -------------------- K1: per-(b,x) prep -------------------------------------
__global__ void prepx_kernel(const float* __restrict__ om,
                             const float* __restrict__ ols,
                             const float* __restrict__ odur,
                             float* __restrict__ out)
{
    int i = blockIdx.x * blockDim.x + threadIdx.x;
    if (i >= Bn*TXn) return;
    int b = i / TXn, x = i % TXn;
    const float* omb = om  + (size_t)b*Cc*TXn + x;
    const float* olb = ols + (size_t)b*Cc*TXn + x;
    float* wS = g_W + (size_t)b*K2*TXn + x;
    float sa = 0.f;
    #pragma unroll 4
    for (int c = 0; c < Cc; c++) {
        float l  = olb[(size_t)c*TXn];
        float sc = expf(-2.f*l);
        float m  = omb[(size_t)c*TXn];
        wS[(size_t)c*TXn]        = sc;
        wS[(size_t)(Cc+c)*TXn]   = m*sc;
        sa += -0.5f*LOG2PI - l - 0.5f*m*m*sc;
    }
    g_rowA[i] = sa;
    g_cnt[i]  = 0;
    out[ODUR_OFF + i] = odur[i];
}

// -------------------- K2: z masking + Z matrix --------------------------------
__global__ void prepz_kernel(const float* __restrict__ z,
                             const int* __restrict__ yl,
                             float* __restrict__ out)
{
    int i = blockIdx.x * blockDim.x + threadIdx.x;
    if (i >= Bn*Cc*TYn) return;
    int b = i / (Cc*TYn);
    int r = i % (Cc*TYn);
    int c = r / TYn;
    int y = r % TYn;
    float zv = z[i];
    if (y >= yl[b]) zv = 0.f;
    out[Z_OFF + i] = zv;
    size_t zb = (size_t)b*K2*TYn;
    g_Z[zb + (size_t)c*TYn + y]      = -0.5f*zv*zv;
    g_Z[zb + (size_t)(Cc+c)*TYn + y] = zv;
}

// -------------------- K3: logp GEMM (128x128 tile, 256 thr, 8x8/thr) ----------
__global__ void __launch_bounds__(256, 2)
gemm_kernel(const int* __restrict__ xl, const int* __restrict__ yl)
{
    int b  = blockIdx.z;
    int x0 = blockIdx.x * 128;
    int y0 = blockIdx.y * 128;
    int xlen = xl[b], ylen = yl[b];
    if (x0 >= xlen || y0 >= ylen) return;

    __shared__ float zs[16][128];   // k x y
    __shared__ float ws[16][128];   // k x x

    int tid  = threadIdx.x;
    int lrow = tid >> 4;            // 0..15
    int lcol = (tid & 15) << 3;     // 0..120
    int ty   = tid >> 4;            // 0..15
    int tx   = tid & 15;            // 0..15

    const float* Zb = g_Z + (size_t)b*K2*TYn;
    const float* Wb = g_W + (size_t)b*K2*TXn;

    float acc[8][8] = {};

    for (int k0 = 0; k0 < K2; k0 += 16) {
        const float* zp = Zb + (size_t)(k0+lrow)*TYn + y0 + lcol;
        const float* wp = Wb + (size_t)(k0+lrow)*TXn + x0 + lcol;
        *(float4*)&zs[lrow][lcol]   = *(const float4*)zp;
        *(float4*)&zs[lrow][lcol+4] = *(const float4*)(zp+4);
        *(float4*)&ws[lrow][lcol]   = *(const float4*)wp;
        *(float4*)&ws[lrow][lcol+4] = *(const float4*)(wp+4);
        __syncthreads();
        #pragma unroll
        for (int k = 0; k < 16; k++) {
            float4 z0 = *(float4*)&zs[k][ty<<3];
            float4 z1 = *(float4*)&zs[k][(ty<<3)+4];
            float4 w0 = *(float4*)&ws[k][tx<<3];
            float4 w1 = *(float4*)&ws[k][(tx<<3)+4];
            float za[8] = {z0.x,z0.y,z0.z,z0.w,z1.x,z1.y,z1.z,z1.w};
            float wa[8] = {w0.x,w0.y,w0.z,w0.w,w1.x,w1.y,w1.z,w1.w};
            #pragma unroll
            for (int i = 0; i < 8; i++)
                #pragma unroll
                for (int j = 0; j < 8; j++)
                    acc[i][j] += za[i]*wa[j];
        }
        __syncthreads();
    }

    float ra[8];
    #pragma unroll
    for (int j = 0; j < 8; j++)
        ra[j] = g_rowA[b*TXn + x0 + (tx<<3) + j];

    #pragma unroll
    for (int i = 0; i < 8; i++) {
        int y = y0 + (ty<<3) + i;
        float* op = g_logpT + ((size_t)b*TYn + y)*TXn + x0 + (tx<<3);
        float4 o0, o1;
        float* p0 = (float*)&o0; float* p1 = (float*)&o1;
        bool yok = (y < ylen);
        #pragma unroll
        for (int j = 0; j < 4; j++) {
            int xa = x0 + (tx<<3) + j;
            int xb = xa + 4;
            p0[j] = (yok && xa < xlen) ? (acc[i][j]   + ra[j])   : 0.f;
            p1[j] = (yok && xb < xlen) ? (acc[i][j+4] + ra[j+4]) : 0.f;
        }
        *(float4*)op       = o0;
        *(float4*)(op + 4) = o1;
    }
}

// -------------------- K4: forward Viterbi (512 threads per batch, x-parallel) --
__global__ void __launch_bounds__(512)
fwd_kernel(const int* __restrict__ xl, const int* __restrict__ yl)
{
    int b = blockIdx.x;
    int x = threadIdx.x;              // one x per thread
    int w = x >> 5, lane = x & 31;
    int xlen = xl[b], ylen = yl[b];

    __shared__ float sb[2][16];       // warp-boundary v values, double-buffered

    // force-stay bits for masked x (x >= xlen), per warp word
    unsigned force;
    int rel = xlen - (w << 5);
    if (rel <= 0)       force = 0xFFFFFFFFu;
    else if (rel < 32)  force = 0xFFFFFFFFu << rel;
    else                force = 0u;

    float v = 0.f;
    if (lane == 31) { sb[0][w] = 0.f; sb[1][w] = 0.f; }

    const float* base = g_logpT + (size_t)b*TYn*TXn + x;
    unsigned* dbase = g_dbits + (size_t)b*TYn*16 + w;

    const int PF = 8;
    float c[PF];
    #pragma unroll
    for (int d = 0; d < PF; d++)
        c[d] = (d < ylen) ? base[(size_t)d*TXn] : 0.f;
    __syncthreads();

    for (int j0 = 0; j0 < ylen; j0 += PF) {
        float cn[PF];
        #pragma unroll
        for (int d = 0; d < PF; d++) {
            int j = j0 + d;
            if (j < ylen) {                      // uniform per block
                int jp = j + PF;
                cn[d] = (jp < ylen) ? base[(size_t)jp*TXn] : 0.f;

                float left = __shfl_up_sync(0xFFFFFFFFu, v, 1);
                if (lane == 0) left = (w == 0) ? NEGV : sb[j & 1][w - 1];

                bool  di = v >= left;
                float vm = di ? v : left;
                float nv = vm + c[d];
                if (x > j) nv = NEGV;

                unsigned bits = __ballot_sync(0xFFFFFFFFu, di) | force;
                if (lane == 0) dbase[(size_t)j*16] = bits;

                v = nv;
                if (lane == 31) sb[(j + 1) & 1][w] = nv;
                __syncthreads();
            }
        }
        #pragma unroll
        for (int d = 0; d < PF; d++) c[d] = cn[d];
    }
}

// -------------------- K5: backtrack + duration count (1 warp per batch) -------
__global__ void __launch_bounds__(32)
bwd_kernel(const int* __restrict__ xl, const int* __restrict__ yl)
{
    int b = blockIdx.x, lane = threadIdx.x;
    int xlen = xl[b], ylen = yl[b];

    for (int j = ylen + lane; j < TYn; j += 32) g_xy[b*TYn + j] = 0;

    int idx = xlen - 1;
    for (int jhi = ylen - 1; jhi >= 0; jhi -= 32) {
        int steps = min(32, jhi + 1);
        int j = jhi - lane;
        int w0 = idx >> 5;                 // idx spans at most 2 words over 32 steps
        unsigned d0 = 0xFFFFFFFFu, d1 = 0xFFFFFFFFu;
        if (lane < steps) {
            const unsigned* p = g_dbits + ((size_t)b*TYn + j)*16;
            d0 = p[w0];
            if (w0 >= 1) d1 = p[w0-1];
        }
        int myidx = 0;
        for (int s = 0; s < steps; s++) {
            unsigned sel  = (w0 == (idx >> 5)) ? d0 : d1;
            unsigned word = __shfl_sync(0xFFFFFFFFu, sel, s);
            if (lane == s) myidx = idx;
            idx += (int)((word >> (idx & 31)) & 1u) - 1;
        }
        if (lane < steps) {
            g_xy[b*TYn + jhi - lane] = myidx;
            atomicAdd(&g_cnt[b*TXn + myidx], 1);
        }
    }
}

// -------------------- K6: y_mean / y_log_scale gathers -------------------------
__global__ void gather_kernel(const float* __restrict__ om,
                              const float* __restrict__ ols,
                              const int* __restrict__ yl,
                              float* __restrict__ out)
{
    int i = blockIdx.x * blockDim.x + threadIdx.x;
    if (i >= Bn*Cc*TYn) return;
    int b = i / (Cc*TYn);
    int r = i % (Cc*TYn);
    int c = r / TYn;
    int y = r % TYn;
    float m = 0.f, s = 0.f;
    if (y < yl[b]) {
        int x = g_xy[b*TYn + y];
        m = om [(size_t)(b*Cc + c)*TXn + x];
        s = ols[(size_t)(b*Cc + c)*TXn + x];
    }
    out[YMEAN_OFF + i] = m;
    out[YLOG_OFF  + i] = s;
}

// -------------------- K7: attn_out (zero + one-hot scatter) --------------------
__global__ void attn_kernel(const int* __restrict__ yl, float* __restrict__ out)
{
    int y = blockIdx.x, b = blockIdx.y, t = threadIdx.x;
    int xi = (y < yl[b]) ? g_xy[b*TYn + y] : -1;
    int x4 = t << 2;
    float4 r = make_float4(0.f, 0.f, 0.f, 0.f);
    if (xi >= x4 && xi < x4 + 4) ((float*)&r)[xi - x4] = 1.0f;
    *(float4*)&out[ATTN_OFF + ((size_t)b*TYn + y)*TXn + x4] = r;
}

// -------------------- K8: o_attn_dur --------------------------------------------
__global__ void dur_kernel(const int* __restrict__ xl, float* __restrict__ out)
{
    int i = blockIdx.x * blockDim.x + threadIdx.x;
    if (i >= Bn*TXn) return;
    int b = i / TXn, x = i % TXn;
    out[OADUR_OFF + i] = (x < xl[b]) ? log1pf((float)g_cnt[i]) : 0.f;
}

// -------------------- launch (single stream) -------------------------------------
extern "C" void kernel_launch(void* const* d_in, const int* in_sizes, int n_in,
                              void* d_out, int out_size)
{
    const float* om   = (const float*)d_in[0];
    const float* ols  = (const float*)d_in[1];
    const float* odur = (const float*)d_in[2];
    const float* z    = (const float*)d_in[3];
    const int*   xlen = (const int*)  d_in[4];
    const int*   ylen = (const int*)  d_in[5];
    float* out = (float*)d_out;

    prepx_kernel<<<(Bn*TXn + 255)/256, 256>>>(om, ols, odur, out);
    prepz_kernel<<<(Bn*Cc*TYn + 255)/256, 256>>>(z, ylen, out);
    gemm_kernel<<<dim3(TXn/128, TYn/128, Bn), 256>>>(xlen, ylen);
    fwd_kernel<<<Bn, 512>>>(xlen, ylen);
    bwd_kernel<<<Bn, 32>>>(xlen, ylen);
    gather_kernel<<<(Bn*Cc*TYn + 255)/256, 256>>>(om, ols, ylen, out);
    attn_kernel<<<dim3(TYn, Bn), 128>>>(ylen, out);
    dur_kernel<<<(Bn*TXn + 255)/256, 256>>>(xlen, out);
}